// round 6
// baseline (speedup 1.0000x reference)
#include <cuda_runtime.h>

#define NW  17
#define PAD 20
#define TPB 128

// Overflow/underflow-safe fast tanh: 1 - 2/(1 + 2^(2*log2(e)*x))
__device__ __forceinline__ float ex2_approx(float x) {
    float y; asm("ex2.approx.f32 %0, %1;" : "=f"(y) : "f"(x)); return y;
}
__device__ __forceinline__ float rcp_approx(float x) {
    float y; asm("rcp.approx.f32 %0, %1;" : "=f"(y) : "f"(x)); return y;
}
__device__ __forceinline__ float fast_tanh(float x) {
    float e = ex2_approx(x * 2.8853900817779268f);   // 2*log2(e)
    return fmaf(-2.0f, rcp_approx(e + 1.0f), 1.0f);
}

// acc[j] (+)= sum_k v[k] * W[k][j]   -- W rows 16B aligned, float4 LDS
template <bool INIT>
__device__ __forceinline__ void matvec(float acc[NW], const float v[NW],
                                       const float W[NW][PAD]) {
#pragma unroll
    for (int k = 0; k < NW; ++k) {
        const float vk = v[k];
        const float4* w4 = reinterpret_cast<const float4*>(W[k]);
#pragma unroll
        for (int q = 0; q < 4; ++q) {
            float4 w = w4[q];
            if (INIT && k == 0) {
                acc[4*q+0] = vk * w.x;
                acc[4*q+1] = vk * w.y;
                acc[4*q+2] = vk * w.z;
                acc[4*q+3] = vk * w.w;
            } else {
                acc[4*q+0] = fmaf(vk, w.x, acc[4*q+0]);
                acc[4*q+1] = fmaf(vk, w.y, acc[4*q+1]);
                acc[4*q+2] = fmaf(vk, w.z, acc[4*q+2]);
                acc[4*q+3] = fmaf(vk, w.w, acc[4*q+3]);
            }
        }
        if (INIT && k == 0) acc[16] = vk * W[k][16];
        else                acc[16] = fmaf(vk, W[k][16], acc[16]);
    }
}

__device__ __forceinline__ void feat(float v[NW], float s,
                                     const float* sWf, const float* sbf) {
#pragma unroll
    for (int j = 0; j < NW; ++j) v[j] = fast_tanh(fmaf(s, sWf[j], sbf[j]));
}

extern "C" __global__ void __launch_bounds__(TPB, 3)
mp_kernel(const float* __restrict__ inp,
          const float* __restrict__ Wf,  const float* __restrict__ bf,
          const float* __restrict__ Wm,  const float* __restrict__ bm,
          const float* __restrict__ Wu,  const float* __restrict__ bu,
          const float* __restrict__ Wr,  const float* __restrict__ br,
          float* __restrict__ out, int B)
{
    __shared__ __align__(16) float sM1[NW][PAD];   // Wm[:17]   (P projection)
    __shared__ __align__(16) float sM2[NW][PAD];   // Wm[17:34] (Q projection)
    __shared__ __align__(16) float sU1[NW][PAD];   // Wu[:17]
    __shared__ __align__(16) float sU2[NW][PAD];   // Wu[17:34]
    __shared__ __align__(16) float sU34[NW][PAD];  // Wu[34:51] + Wu[51:68]
    __shared__ float sWf[NW], sbf[NW], sbm[NW], sbu[NW], sWr[5 * NW], sbr;

    for (int idx = threadIdx.x; idx < NW * NW; idx += TPB) {
        int k = idx / NW, j = idx % NW;
        sM1[k][j]  = Wm[idx];
        sM2[k][j]  = Wm[NW * NW + idx];
        sU1[k][j]  = Wu[idx];
        sU2[k][j]  = Wu[NW * NW + idx];
        sU34[k][j] = Wu[2 * NW * NW + idx] + Wu[3 * NW * NW + idx];
    }
    if (threadIdx.x < NW) {
        sWf[threadIdx.x] = Wf[threadIdx.x];
        sbf[threadIdx.x] = bf[threadIdx.x];
        sbm[threadIdx.x] = bm[threadIdx.x];
        sbu[threadIdx.x] = bu[threadIdx.x];
    }
    for (int idx = threadIdx.x; idx < 5 * NW; idx += TPB) sWr[idx] = Wr[idx];
    if (threadIdx.x == 0) sbr = br[0];
    __syncthreads();

    const int row = blockIdx.x * TPB + threadIdx.x;
    if (row >= B) return;

    float xs[5];
#pragma unroll
    for (int i = 0; i < 5; ++i) xs[i] = inp[row * 5 + i];

    // ---- Phase 0: Q projections for nodes a..d (held across phase 1) ----
    float Qa[NW], Qb[NW], Qc[NW], Qd[NW];
    {
        float v[NW];
        feat(v, xs[0], sWf, sbf); matvec<true>(Qa, v, sM2);
        feat(v, xs[1], sWf, sbf); matvec<true>(Qb, v, sM2);
        feat(v, xs[2], sWf, sbf); matvec<true>(Qc, v, sM2);
        feat(v, xs[3], sWf, sbf); matvec<true>(Qd, v, sM2);
    }

    float o = sbr;

    // ---- Phase 1: one node at a time; working set dies before next node ----
    // node x: m1 = tanh(P_x + Qn + bm) -> U1 ; m2 = tanh(P_x + Qp + bm) -> U2
    //   a: (Qn=Qb, Qp=Qd)  b: (Qa, Qc)  c: (Qb, Qd)  d: (Qc, Qa)
#pragma unroll
    for (int node = 0; node < 4; ++node) {
        const float* Qn = (node == 0) ? Qb : (node == 1) ? Qa : (node == 2) ? Qb : Qc;
        const float* Qp = (node == 0) ? Qd : (node == 1) ? Qc : (node == 2) ? Qd : Qa;

        float v[NW], P[NW], acc[NW], m[NW];
        feat(v, xs[node], sWf, sbf);
        matvec<true>(P, v, sM1);
#pragma unroll
        for (int j = 0; j < NW; ++j) acc[j] = sbu[j];
        matvec<false>(acc, v, sU34);           // v dies here

#pragma unroll
        for (int j = 0; j < NW; ++j) m[j] = fast_tanh(P[j] + Qn[j] + sbm[j]);
        matvec<false>(acc, m, sU1);

#pragma unroll
        for (int j = 0; j < NW; ++j) m[j] = fast_tanh(P[j] + Qp[j] + sbm[j]);   // P dies here
        matvec<false>(acc, m, sU2);

#pragma unroll
        for (int j = 0; j < NW; ++j)
            o = fmaf(fast_tanh(acc[j]), sWr[node * NW + j], o);
    }

    // ---- node e: Ue = tanh(e@U34 + bu) ----
    {
        float v[NW], acc[NW];
        feat(v, xs[4], sWf, sbf);
#pragma unroll
        for (int j = 0; j < NW; ++j) acc[j] = sbu[j];
        matvec<false>(acc, v, sU34);
#pragma unroll
        for (int j = 0; j < NW; ++j)
            o = fmaf(fast_tanh(acc[j]), sWr[4 * NW + j], o);
    }

    out[row] = o;
}

extern "C" void kernel_launch(void* const* d_in, const int* in_sizes, int n_in,
                              void* d_out, int out_size)
{
    const float* inp = (const float*)d_in[0];
    const float* Wf  = (const float*)d_in[1];
    const float* bf  = (const float*)d_in[2];
    const float* Wm  = (const float*)d_in[3];
    const float* bm  = (const float*)d_in[4];
    const float* Wu  = (const float*)d_in[5];
    const float* bu  = (const float*)d_in[6];
    const float* Wr  = (const float*)d_in[7];
    const float* br  = (const float*)d_in[8];
    float* out = (float*)d_out;

    const int B = in_sizes[0] / 5;
    const int grid = (B + TPB - 1) / TPB;
    mp_kernel<<<grid, TPB>>>(inp, Wf, bf, Wm, bm, Wu, bu, Wr, br, out, B);
}

// round 8
// speedup vs baseline: 1.0168x; 1.0168x over previous
#include <cuda_runtime.h>

#define NW  17
#define PAD 20
#define TPB 128

// Overflow/underflow-safe fast tanh: 1 - 2/(1 + 2^(2*log2(e)*x))
__device__ __forceinline__ float ex2_approx(float x) {
    float y; asm("ex2.approx.f32 %0, %1;" : "=f"(y) : "f"(x)); return y;
}
__device__ __forceinline__ float rcp_approx(float x) {
    float y; asm("rcp.approx.f32 %0, %1;" : "=f"(y) : "f"(x)); return y;
}
__device__ __forceinline__ float fast_tanh(float x) {
    float e = ex2_approx(x * 2.8853900817779268f);   // 2*log2(e)
    return fmaf(-2.0f, rcp_approx(e + 1.0f), 1.0f);
}

// acc[j] (+)= sum_k v[k] * W[k][j]   -- W rows 16B aligned, float4 LDS
template <bool INIT>
__device__ __forceinline__ void matvec(float acc[NW], const float v[NW],
                                       const float W[NW][PAD]) {
#pragma unroll
    for (int k = 0; k < NW; ++k) {
        const float vk = v[k];
        const float4* w4 = reinterpret_cast<const float4*>(W[k]);
#pragma unroll
        for (int q = 0; q < 4; ++q) {
            float4 w = w4[q];
            if (INIT && k == 0) {
                acc[4*q+0] = vk * w.x;
                acc[4*q+1] = vk * w.y;
                acc[4*q+2] = vk * w.z;
                acc[4*q+3] = vk * w.w;
            } else {
                acc[4*q+0] = fmaf(vk, w.x, acc[4*q+0]);
                acc[4*q+1] = fmaf(vk, w.y, acc[4*q+1]);
                acc[4*q+2] = fmaf(vk, w.z, acc[4*q+2]);
                acc[4*q+3] = fmaf(vk, w.w, acc[4*q+3]);
            }
        }
        if (INIT && k == 0) acc[16] = vk * W[k][16];
        else                acc[16] = fmaf(vk, W[k][16], acc[16]);
    }
}

__device__ __forceinline__ void feat(float v[NW], float s,
                                     const float* sWf, const float* sbf) {
#pragma unroll
    for (int j = 0; j < NW; ++j) v[j] = fast_tanh(fmaf(s, sWf[j], sbf[j]));
}

extern "C" __global__ void __launch_bounds__(TPB, 3)
mp_kernel(const float* __restrict__ inp,
          const float* __restrict__ Wf,  const float* __restrict__ bf,
          const float* __restrict__ Wm,  const float* __restrict__ bm,
          const float* __restrict__ Wu,  const float* __restrict__ bu,
          const float* __restrict__ Wr,  const float* __restrict__ br,
          float* __restrict__ out, int B)
{
    __shared__ __align__(16) float sM1[NW][PAD];   // Wm[:17]   (P projection)
    __shared__ __align__(16) float sM2[NW][PAD];   // Wm[17:34] (Q projection)
    __shared__ __align__(16) float sU1[NW][PAD];   // Wu[:17]
    __shared__ __align__(16) float sU2[NW][PAD];   // Wu[17:34]
    __shared__ __align__(16) float sU34[NW][PAD];  // Wu[34:51] + Wu[51:68]
    __shared__ float sWf[NW], sbf[NW], sbm[NW], sbu[NW], sWr[5 * NW], sbr;

    for (int idx = threadIdx.x; idx < NW * NW; idx += TPB) {
        int k = idx / NW, j = idx % NW;
        sM1[k][j]  = Wm[idx];
        sM2[k][j]  = Wm[NW * NW + idx];
        sU1[k][j]  = Wu[idx];
        sU2[k][j]  = Wu[NW * NW + idx];
        sU34[k][j] = Wu[2 * NW * NW + idx] + Wu[3 * NW * NW + idx];
    }
    if (threadIdx.x < NW) {
        sWf[threadIdx.x] = Wf[threadIdx.x];
        sbf[threadIdx.x] = bf[threadIdx.x];
        sbm[threadIdx.x] = bm[threadIdx.x];
        sbu[threadIdx.x] = bu[threadIdx.x];
    }
    for (int idx = threadIdx.x; idx < 5 * NW; idx += TPB) sWr[idx] = Wr[idx];
    if (threadIdx.x == 0) sbr = br[0];
    __syncthreads();

    const int row = blockIdx.x * TPB + threadIdx.x;
    if (row >= B) return;

    const float x0 = inp[row * 5 + 0];
    const float x1 = inp[row * 5 + 1];
    const float x2 = inp[row * 5 + 2];
    const float x3 = inp[row * 5 + 3];
    const float x4 = inp[row * 5 + 4];

    // ---- Phase 0: Q projections for nodes a..d (held across phase 1) ----
    float Qa[NW], Qb[NW], Qc[NW], Qd[NW];
    {
        float v[NW];
        feat(v, x0, sWf, sbf); matvec<true>(Qa, v, sM2);
        feat(v, x1, sWf, sbf); matvec<true>(Qb, v, sM2);
        feat(v, x2, sWf, sbf); matvec<true>(Qc, v, sM2);
        feat(v, x3, sWf, sbf); matvec<true>(Qd, v, sM2);
    }

    float o = sbr;

    // ---- Phase 1: one node at a time, macro-expanded so every Q reference
    //      is a NAMED register array (no pointer selection -> no local-mem
    //      demotion, which is what destroyed R6: DRAM=49.6%, issue=9.5%).
    // node x: m1 = tanh(P + Q_next + bm) @ U1 ; m2 = tanh(P + Q_prev + bm) @ U2
#define DO_NODE(XS, QN, QP, WOFF)                                          \
    {                                                                      \
        float v[NW], P[NW], acc[NW], m[NW];                                \
        feat(v, XS, sWf, sbf);                                             \
        matvec<true>(P, v, sM1);                                           \
        _Pragma("unroll")                                                  \
        for (int j = 0; j < NW; ++j) acc[j] = sbu[j];                      \
        matvec<false>(acc, v, sU34);                                       \
        _Pragma("unroll")                                                  \
        for (int j = 0; j < NW; ++j) m[j] = fast_tanh(P[j] + QN[j] + sbm[j]); \
        matvec<false>(acc, m, sU1);                                        \
        _Pragma("unroll")                                                  \
        for (int j = 0; j < NW; ++j) m[j] = fast_tanh(P[j] + QP[j] + sbm[j]); \
        matvec<false>(acc, m, sU2);                                        \
        _Pragma("unroll")                                                  \
        for (int j = 0; j < NW; ++j)                                       \
            o = fmaf(fast_tanh(acc[j]), sWr[(WOFF) + j], o);               \
    }

    DO_NODE(x0, Qb, Qd, 0)        // a: Mab -> U1, Mad -> U2
    DO_NODE(x1, Qa, Qc, NW)       // b: Mba -> U1, Mbc -> U2
    DO_NODE(x2, Qb, Qd, 2 * NW)   // c: Mcb -> U1, Mcd -> U2
    DO_NODE(x3, Qc, Qa, 3 * NW)   // d: Mdc -> U1, Mda -> U2
#undef DO_NODE

    // ---- node e: Ue = tanh(e@U34 + bu) ----
    {
        float v[NW], acc[NW];
        feat(v, x4, sWf, sbf);
#pragma unroll
        for (int j = 0; j < NW; ++j) acc[j] = sbu[j];
        matvec<false>(acc, v, sU34);
#pragma unroll
        for (int j = 0; j < NW; ++j)
            o = fmaf(fast_tanh(acc[j]), sWr[4 * NW + j], o);
    }

    out[row] = o;
}

extern "C" void kernel_launch(void* const* d_in, const int* in_sizes, int n_in,
                              void* d_out, int out_size)
{
    const float* inp = (const float*)d_in[0];
    const float* Wf  = (const float*)d_in[1];
    const float* bf  = (const float*)d_in[2];
    const float* Wm  = (const float*)d_in[3];
    const float* bm  = (const float*)d_in[4];
    const float* Wu  = (const float*)d_in[5];
    const float* bu  = (const float*)d_in[6];
    const float* Wr  = (const float*)d_in[7];
    const float* br  = (const float*)d_in[8];
    float* out = (float*)d_out;

    const int B = in_sizes[0] / 5;
    const int grid = (B + TPB - 1) / TPB;
    mp_kernel<<<grid, TPB>>>(inp, Wf, bf, Wm, bm, Wu, bu, Wr, br, out, B);
}

// round 10
// speedup vs baseline: 1.0846x; 1.0667x over previous
#include <cuda_runtime.h>

#define NW  17
#define PAD 20
#define TPB 128

// Overflow/underflow-safe fast tanh: 1 - 2/(1 + 2^(2*log2(e)*x))
__device__ __forceinline__ float ex2_approx(float x) {
    float y; asm("ex2.approx.f32 %0, %1;" : "=f"(y) : "f"(x)); return y;
}
__device__ __forceinline__ float rcp_approx(float x) {
    float y; asm("rcp.approx.f32 %0, %1;" : "=f"(y) : "f"(x)); return y;
}
__device__ __forceinline__ float fast_tanh(float x) {
    float e = ex2_approx(x * 2.8853900817779268f);   // 2*log2(e)
    return fmaf(-2.0f, rcp_approx(e + 1.0f), 1.0f);
}

// acc[j] (+)= sum_k v[k] * W[k][j]   -- W rows 16B aligned, float4 LDS
template <bool INIT>
__device__ __forceinline__ void matvec(float acc[NW], const float v[NW],
                                       const float W[NW][PAD]) {
#pragma unroll
    for (int k = 0; k < NW; ++k) {
        const float vk = v[k];
        const float4* w4 = reinterpret_cast<const float4*>(W[k]);
#pragma unroll
        for (int q = 0; q < 4; ++q) {
            float4 w = w4[q];
            if (INIT && k == 0) {
                acc[4*q+0] = vk * w.x;
                acc[4*q+1] = vk * w.y;
                acc[4*q+2] = vk * w.z;
                acc[4*q+3] = vk * w.w;
            } else {
                acc[4*q+0] = fmaf(vk, w.x, acc[4*q+0]);
                acc[4*q+1] = fmaf(vk, w.y, acc[4*q+1]);
                acc[4*q+2] = fmaf(vk, w.z, acc[4*q+2]);
                acc[4*q+3] = fmaf(vk, w.w, acc[4*q+3]);
            }
        }
        if (INIT && k == 0) acc[16] = vk * W[k][16];
        else                acc[16] = fmaf(vk, W[k][16], acc[16]);
    }
}

__device__ __forceinline__ void feat(float v[NW], float s,
                                     const float* sWf, const float* sbf) {
#pragma unroll
    for (int j = 0; j < NW; ++j) v[j] = fast_tanh(fmaf(s, sWf[j], sbf[j]));
}

extern "C" __global__ void __launch_bounds__(TPB, 3)
mp_kernel(const float* __restrict__ inp,
          const float* __restrict__ Wf,  const float* __restrict__ bf,
          const float* __restrict__ Wm,  const float* __restrict__ bm,
          const float* __restrict__ Wu,  const float* __restrict__ bu,
          const float* __restrict__ Wr,  const float* __restrict__ br,
          float* __restrict__ out, int B)
{
    __shared__ __align__(16) float sM1[NW][PAD];   // Wm[:17]   (P projection)
    __shared__ __align__(16) float sM2[NW][PAD];   // Wm[17:34] (Q projection)
    __shared__ __align__(16) float sU1[NW][PAD];   // Wu[:17]
    __shared__ __align__(16) float sU2[NW][PAD];   // Wu[17:34]
    __shared__ __align__(16) float sU34[NW][PAD];  // Wu[34:51] + Wu[51:68]
    __shared__ float sWf[NW], sbf[NW], sbm[NW], sbu[NW], sWr[5 * NW], sbr;

    for (int idx = threadIdx.x; idx < NW * NW; idx += TPB) {
        int k = idx / NW, j = idx % NW;
        sM1[k][j]  = Wm[idx];
        sM2[k][j]  = Wm[NW * NW + idx];
        sU1[k][j]  = Wu[idx];
        sU2[k][j]  = Wu[NW * NW + idx];
        sU34[k][j] = Wu[2 * NW * NW + idx] + Wu[3 * NW * NW + idx];
    }
    if (threadIdx.x < NW) {
        sWf[threadIdx.x] = Wf[threadIdx.x];
        sbf[threadIdx.x] = bf[threadIdx.x];
        sbm[threadIdx.x] = bm[threadIdx.x];
        sbu[threadIdx.x] = bu[threadIdx.x];
    }
    for (int idx = threadIdx.x; idx < 5 * NW; idx += TPB) sWr[idx] = Wr[idx];
    if (threadIdx.x == 0) sbr = br[0];
    __syncthreads();

    const int row = blockIdx.x * TPB + threadIdx.x;
    if (row >= B) return;

    const float x0 = inp[row * 5 + 0];
    const float x1 = inp[row * 5 + 1];
    const float x2 = inp[row * 5 + 2];
    const float x3 = inp[row * 5 + 3];
    const float x4 = inp[row * 5 + 4];

    float o = sbr;

    // One node fully retired at a time. NOTHING is held across nodes except
    // the readout scalar. Q projections are recomputed from the scalar input
    // per use (+19% FLOPs) so peak live set is P+acc+v+Q = 68 floats -- far
    // under the 170-reg cap, eliminating the local-memory demotion that held
    // R6/R8 at DRAM=50%, issue=9.6%.
    // node x: m1 = tanh(Px + Q_next + bm) @ U1 ; m2 = tanh(Px + Q_prev + bm) @ U2
#define DO_NODE(X, XN, XP, WOFF)                                            \
    {                                                                       \
        float v[NW], P[NW], acc[NW], Q[NW], m[NW];                          \
        feat(v, X, sWf, sbf);                                               \
        matvec<true>(P, v, sM1);                                            \
        _Pragma("unroll")                                                   \
        for (int j = 0; j < NW; ++j) acc[j] = sbu[j];                       \
        matvec<false>(acc, v, sU34);                                        \
        feat(v, XN, sWf, sbf);                                              \
        matvec<true>(Q, v, sM2);                                            \
        _Pragma("unroll")                                                   \
        for (int j = 0; j < NW; ++j) m[j] = fast_tanh(P[j] + Q[j] + sbm[j]);\
        matvec<false>(acc, m, sU1);                                         \
        feat(v, XP, sWf, sbf);                                              \
        matvec<true>(Q, v, sM2);                                            \
        _Pragma("unroll")                                                   \
        for (int j = 0; j < NW; ++j) m[j] = fast_tanh(P[j] + Q[j] + sbm[j]);\
        matvec<false>(acc, m, sU2);                                         \
        _Pragma("unroll")                                                   \
        for (int j = 0; j < NW; ++j)                                        \
            o = fmaf(fast_tanh(acc[j]), sWr[(WOFF) + j], o);                \
    }

    DO_NODE(x0, x1, x3, 0)        // a: Mab -> U1, Mad -> U2
    DO_NODE(x1, x0, x2, NW)       // b: Mba -> U1, Mbc -> U2
    DO_NODE(x2, x1, x3, 2 * NW)   // c: Mcb -> U1, Mcd -> U2
    DO_NODE(x3, x2, x0, 3 * NW)   // d: Mdc -> U1, Mda -> U2
#undef DO_NODE

    // ---- node e: Ue = tanh(e@U34 + bu) ----
    {
        float v[NW], acc[NW];
        feat(v, x4, sWf, sbf);
#pragma unroll
        for (int j = 0; j < NW; ++j) acc[j] = sbu[j];
        matvec<false>(acc, v, sU34);
#pragma unroll
        for (int j = 0; j < NW; ++j)
            o = fmaf(fast_tanh(acc[j]), sWr[4 * NW + j], o);
    }

    out[row] = o;
}

extern "C" void kernel_launch(void* const* d_in, const int* in_sizes, int n_in,
                              void* d_out, int out_size)
{
    const float* inp = (const float*)d_in[0];
    const float* Wf  = (const float*)d_in[1];
    const float* bf  = (const float*)d_in[2];
    const float* Wm  = (const float*)d_in[3];
    const float* bm  = (const float*)d_in[4];
    const float* Wu  = (const float*)d_in[5];
    const float* bu  = (const float*)d_in[6];
    const float* Wr  = (const float*)d_in[7];
    const float* br  = (const float*)d_in[8];
    float* out = (float*)d_out;

    const int B = in_sizes[0] / 5;
    const int grid = (B + TPB - 1) / TPB;
    mp_kernel<<<grid, TPB>>>(inp, Wf, bf, Wm, bm, Wu, bu, Wr, br, out, B);
}